// round 3
// baseline (speedup 1.0000x reference)
#include <cuda_runtime.h>

// Problem constants (FullAttention_73650099192077)
#define B_SZ 4
#define L_Q  2048
#define S_K  2048
#define H_N  8
#define E_N  64
#define D_N  64

#define BM 64           // query rows per CTA
#define BN 64           // key cols per S-tile
#define QSTR 68         // padded row stride (floats) for transposed Q/K tiles
#define NTHREADS 256

// Dynamic smem layout (floats):
//   qT  [64][QSTR]   (E-major, pre-scaled Q^T)
//   kT  [64][QSTR]   (E-major K^T)  -- aliased with p[64][64] between phases
//   vs  [64][64]     (V tile, row-major [c][d])
#define SMEM_FLOATS (2 * 64 * QSTR + 64 * 64)

__global__ __launch_bounds__(NTHREADS)
void fullattn_fp32_kernel(const float* __restrict__ Q,
                          const float* __restrict__ K,
                          const float* __restrict__ V,
                          float* __restrict__ O)
{
    extern __shared__ float smem[];
    float* qT = smem;                    // [64][QSTR]
    float* kT = smem + 64 * QSTR;        // [64][QSTR]; reused as p[64][64]
    float* vs = smem + 2 * 64 * QSTR;    // [64][64]

    const int t  = threadIdx.x;
    const int tx = t & 15;               // 16 threads per row-group (cols)
    const int ty = t >> 4;               // 16 row-groups of 4 rows
    const int l0 = blockIdx.x * BM;
    const int bh = blockIdx.y;
    const int b  = bh >> 3;              // / H_N
    const int h  = bh & 7;               // % H_N

    const float scale = 0.125f;          // 1/sqrt(E)

    // ---- load Q tile, transposed + pre-scaled: qT[e][r] = Q[b, l0+r, h, e] * scale
    {
        const float* qbase = Q + ((b * L_Q + l0) * H_N + h) * E_N;
        #pragma unroll
        for (int kk = 0; kk < 4; kk++) {
            int idx = kk * NTHREADS + t;
            int r = idx >> 4;
            int g = idx & 15;
            float4 qv = *reinterpret_cast<const float4*>(qbase + r * (H_N * E_N) + g * 4);
            qT[(g * 4 + 0) * QSTR + r] = qv.x * scale;
            qT[(g * 4 + 1) * QSTR + r] = qv.y * scale;
            qT[(g * 4 + 2) * QSTR + r] = qv.z * scale;
            qT[(g * 4 + 3) * QSTR + r] = qv.w * scale;
        }
    }

    // Online-softmax state: 4 rows per thread group; m,l replicated over the 16 tx lanes
    float m[4], l[4], o[4][4];
    #pragma unroll
    for (int i = 0; i < 4; i++) {
        m[i] = -1e30f;
        l[i] = 0.0f;
        #pragma unroll
        for (int j = 0; j < 4; j++) o[i][j] = 0.0f;
    }

    const float* kbase = K + ((b * S_K) * H_N + h) * E_N;
    const float* vbase = V + ((b * S_K) * H_N + h) * D_N;

    for (int s0 = 0; s0 < S_K; s0 += BN) {
        // ---- load K^T (kT[e][c]) and V (vs[c][d]) tiles
        #pragma unroll
        for (int kk = 0; kk < 4; kk++) {
            int idx = kk * NTHREADS + t;
            int c = idx >> 4;
            int g = idx & 15;
            float4 kv = *reinterpret_cast<const float4*>(kbase + (s0 + c) * (H_N * E_N) + g * 4);
            kT[(g * 4 + 0) * QSTR + c] = kv.x;
            kT[(g * 4 + 1) * QSTR + c] = kv.y;
            kT[(g * 4 + 2) * QSTR + c] = kv.z;
            kT[(g * 4 + 3) * QSTR + c] = kv.w;
            float4 vv = *reinterpret_cast<const float4*>(vbase + (s0 + c) * (H_N * D_N) + g * 4);
            *reinterpret_cast<float4*>(&vs[c * 64 + g * 4]) = vv;
        }
        __syncthreads();

        // ---- scores: s[i][j] = sum_e qT[e][ty*4+i] * kT[e][tx*4+j]  (scale folded into qT)
        float sacc[4][4];
        #pragma unroll
        for (int i = 0; i < 4; i++)
            #pragma unroll
            for (int j = 0; j < 4; j++) sacc[i][j] = 0.0f;

        #pragma unroll 16
        for (int e = 0; e < 64; e++) {
            float4 qv = *reinterpret_cast<const float4*>(&qT[e * QSTR + ty * 4]);
            float4 kv = *reinterpret_cast<const float4*>(&kT[e * QSTR + tx * 4]);
            float qa[4] = {qv.x, qv.y, qv.z, qv.w};
            float ka[4] = {kv.x, kv.y, kv.z, kv.w};
            #pragma unroll
            for (int i = 0; i < 4; i++)
                #pragma unroll
                for (int j = 0; j < 4; j++)
                    sacc[i][j] = fmaf(qa[i], ka[j], sacc[i][j]);
        }
        __syncthreads();   // everyone done reading kT -> safe to overwrite with p

        // ---- online softmax (row reductions across the 16 tx lanes via shfl)
        float p[4][4];
        #pragma unroll
        for (int i = 0; i < 4; i++) {
            float tm = sacc[i][0];
            #pragma unroll
            for (int j = 1; j < 4; j++) tm = fmaxf(tm, sacc[i][j]);
            #pragma unroll
            for (int off = 1; off < 16; off <<= 1)
                tm = fmaxf(tm, __shfl_xor_sync(0xffffffffu, tm, off));

            float nm = fmaxf(m[i], tm);
            float alpha = __expf(m[i] - nm);
            m[i] = nm;

            float rs = 0.0f;
            #pragma unroll
            for (int j = 0; j < 4; j++) {
                p[i][j] = __expf(sacc[i][j] - nm);
                rs += p[i][j];
            }
            #pragma unroll
            for (int off = 1; off < 16; off <<= 1)
                rs += __shfl_xor_sync(0xffffffffu, rs, off);

            l[i] = l[i] * alpha + rs;
            #pragma unroll
            for (int j = 0; j < 4; j++) o[i][j] *= alpha;
        }

        // ---- write p into the kT buffer (stride 64), float4 per row
        float* ps = kT;
        #pragma unroll
        for (int i = 0; i < 4; i++) {
            float4 pv = make_float4(p[i][0], p[i][1], p[i][2], p[i][3]);
            *reinterpret_cast<float4*>(&ps[(ty * 4 + i) * 64 + tx * 4]) = pv;
        }
        __syncthreads();   // p visible to all

        // ---- PV: o[i][j] += sum_c p[ty*4+i][c] * vs[c][tx*4+j]
        #pragma unroll 8
        for (int c = 0; c < 64; c++) {
            float4 vv = *reinterpret_cast<const float4*>(&vs[c * 64 + tx * 4]);
            float va[4] = {vv.x, vv.y, vv.z, vv.w};
            float pa[4];
            #pragma unroll
            for (int i = 0; i < 4; i++) pa[i] = ps[(ty * 4 + i) * 64 + c];  // broadcast
            #pragma unroll
            for (int i = 0; i < 4; i++)
                #pragma unroll
                for (int j = 0; j < 4; j++)
                    o[i][j] = fmaf(pa[i], va[j], o[i][j]);
        }
        __syncthreads();   // done with ps/vs -> next tile load may overwrite
    }

    // ---- epilogue: normalize and store O[b, l0+r, h, d]
    float* obase = O + ((b * L_Q + l0) * H_N + h) * D_N;
    #pragma unroll
    for (int i = 0; i < 4; i++) {
        float inv = 1.0f / l[i];
        float4 ov = make_float4(o[i][0] * inv, o[i][1] * inv, o[i][2] * inv, o[i][3] * inv);
        *reinterpret_cast<float4*>(obase + (ty * 4 + i) * (H_N * D_N) + tx * 4) = ov;
    }
}

extern "C" void kernel_launch(void* const* d_in, const int* in_sizes, int n_in,
                              void* d_out, int out_size)
{
    const float* Q = (const float*)d_in[0];
    const float* K = (const float*)d_in[1];
    const float* V = (const float*)d_in[2];
    float* O = (float*)d_out;

    (void)in_sizes; (void)n_in; (void)out_size;

    // 51200 B dynamic smem > 48KB default -> raise the cap (idempotent, capture-safe)
    cudaFuncSetAttribute(fullattn_fp32_kernel,
                         cudaFuncAttributeMaxDynamicSharedMemorySize,
                         SMEM_FLOATS * (int)sizeof(float));

    dim3 grid(L_Q / BM, B_SZ * H_N);   // 32 x 32 CTAs
    fullattn_fp32_kernel<<<grid, NTHREADS, SMEM_FLOATS * sizeof(float)>>>(Q, K, V, O);
}

// round 5
// speedup vs baseline: 2.7718x; 2.7718x over previous
#include <cuda_runtime.h>
#include <cuda_bf16.h>

// Problem constants (FullAttention_73650099192077)
#define B_SZ 4
#define L_Q  2048
#define S_K  2048
#define H_N  8
#define E_N  64
#define D_N  64

#define BM   128           // query rows per CTA (8 warps x 16 rows)
#define BN   64            // keys per tile
#define NT   256
#define NTILES (S_K / BN)

// SMEM: four bf16 buffers [64 rows][64 cols] = 8192 B each, 128 B/row, XOR-swizzled.
// Q staging (128 rows x 64 bf16 = 16 KB) aliases KH+KL before the main loop.
#define SM_KH 0
#define SM_KL 8192
#define SM_VH 16384
#define SM_VL 24576
#define SM_BYTES 32768

static __device__ __forceinline__ unsigned smem_u32(const void* p) {
    unsigned a;
    asm("{ .reg .u64 t; cvta.to.shared.u64 t, %1; cvt.u32.u64 %0, t; }" : "=r"(a) : "l"(p));
    return a;
}

// row-swizzled byte address: row*128 + (bytecol XOR ((row&7)<<4))
static __device__ __forceinline__ unsigned swz(unsigned base, int row, int bytecol) {
    return base + (unsigned)(row * 128) + (unsigned)(bytecol ^ ((row & 7) << 4));
}

static __device__ __forceinline__ void ldsm_x4(unsigned* r, unsigned addr) {
    asm volatile("ldmatrix.sync.aligned.m8n8.x4.shared.b16 {%0,%1,%2,%3}, [%4];"
                 : "=r"(r[0]), "=r"(r[1]), "=r"(r[2]), "=r"(r[3]) : "r"(addr));
}
static __device__ __forceinline__ void ldsm_x4_t(unsigned* r, unsigned addr) {
    asm volatile("ldmatrix.sync.aligned.m8n8.x4.trans.shared.b16 {%0,%1,%2,%3}, [%4];"
                 : "=r"(r[0]), "=r"(r[1]), "=r"(r[2]), "=r"(r[3]) : "r"(addr));
}

// D += A(16x16 bf16) * B(16x8 bf16), fp32 accum
static __device__ __forceinline__ void mma16816(float* c, const unsigned* a, unsigned b0, unsigned b1) {
    asm volatile("mma.sync.aligned.m16n8k16.row.col.f32.bf16.bf16.f32 "
                 "{%0,%1,%2,%3}, {%4,%5,%6,%7}, {%8,%9}, {%0,%1,%2,%3};"
                 : "+f"(c[0]), "+f"(c[1]), "+f"(c[2]), "+f"(c[3])
                 : "r"(a[0]), "r"(a[1]), "r"(a[2]), "r"(a[3]), "r"(b0), "r"(b1));
}

// split fp32 pair -> bf16x2 hi + bf16x2 lo
static __device__ __forceinline__ void split2(float x, float y, unsigned& h, unsigned& l) {
    __nv_bfloat162 hb = __floats2bfloat162_rn(x, y);
    float hx = __low2float(hb), hy = __high2float(hb);
    __nv_bfloat162 lb = __floats2bfloat162_rn(x - hx, y - hy);
    h = *reinterpret_cast<unsigned*>(&hb);
    l = *reinterpret_cast<unsigned*>(&lb);
}

__global__ __launch_bounds__(NT, 1)
void fullattn_hmma_kernel(const float* __restrict__ Q,
                          const float* __restrict__ K,
                          const float* __restrict__ V,
                          float* __restrict__ O)
{
    __shared__ __align__(128) char smbuf[SM_BYTES];
    const unsigned sb = smem_u32(smbuf);

    const int t    = threadIdx.x;
    const int wid  = t >> 5;
    const int lane = t & 31;
    const int g    = lane >> 2;     // quad row within fragment
    const int tg   = lane & 3;      // thread-in-quad (column pairs)
    const int l0   = blockIdx.x * BM;
    const int bh   = blockIdx.y;
    const int b    = bh >> 3;
    const int h    = bh & 7;

    // ============ Q: load, scale, split; stage through smem; ldmatrix to A-frags ============
    unsigned qh[16], ql[16];   // [kb][4] A fragments, kb = 0..3
    {
        const int r  = t >> 1;                 // 128 rows, 2 threads/row
        const int e0 = (t & 1) << 5;           // 32 elems each
        const float* src = Q + ((size_t)(b * L_Q + l0 + r) * H_N + h) * E_N + e0;
        unsigned hi[16], lo[16];
        #pragma unroll
        for (int j = 0; j < 8; j++) {
            float4 v = *reinterpret_cast<const float4*>(src + j * 4);
            split2(v.x * 0.125f, v.y * 0.125f, hi[2*j],   lo[2*j]);
            split2(v.z * 0.125f, v.w * 0.125f, hi[2*j+1], lo[2*j+1]);
        }
        // stage hi (Q rows use 128 B rows, same swizzle; stage spans SM_KH..SM_KL)
        #pragma unroll
        for (int c4 = 0; c4 < 4; c4++)
            *reinterpret_cast<uint4*>((char*)smbuf + (swz(0, r, e0*2 + c4*16)))
                = make_uint4(hi[4*c4], hi[4*c4+1], hi[4*c4+2], hi[4*c4+3]);
        __syncthreads();
        #pragma unroll
        for (int kb = 0; kb < 4; kb++)
            ldsm_x4(&qh[kb*4], swz(sb, wid*16 + (lane & 15), kb*32 + (lane >> 4)*16));
        __syncthreads();
        // stage lo
        #pragma unroll
        for (int c4 = 0; c4 < 4; c4++)
            *reinterpret_cast<uint4*>((char*)smbuf + (swz(0, r, e0*2 + c4*16)))
                = make_uint4(lo[4*c4], lo[4*c4+1], lo[4*c4+2], lo[4*c4+3]);
        __syncthreads();
        #pragma unroll
        for (int kb = 0; kb < 4; kb++)
            ldsm_x4(&ql[kb*4], swz(sb, wid*16 + (lane & 15), kb*32 + (lane >> 4)*16));
        __syncthreads();
    }

    // ============ main loop state ============
    float o[8][4];                   // O fragments: [dblock][c0..c3]
    #pragma unroll
    for (int j = 0; j < 8; j++)
        #pragma unroll
        for (int i = 0; i < 4; i++) o[j][i] = 0.0f;
    float m0 = -1e30f, m1 = -1e30f;  // row maxima (rows g, g+8)
    float l0s = 0.0f, l1s = 0.0f;    // row sums

    // per-thread gmem load role for K/V tiles: row c, 16 floats at e0
    const int kc  = t >> 2;
    const int ke0 = (t & 3) << 4;
    const float* kptr = K + ((size_t)(b * S_K + kc) * H_N + h) * E_N + ke0;
    const float* vptr = V + ((size_t)(b * S_K + kc) * H_N + h) * D_N + ke0;
    const size_t tstep = (size_t)BN * H_N * E_N;

    // ---- prologue: load tile 0 into smem ----
    {
        unsigned kh[8], kl[8], vh[8], vl[8];
        #pragma unroll
        for (int j = 0; j < 4; j++) {
            float4 kv = *reinterpret_cast<const float4*>(kptr + j * 4);
            split2(kv.x, kv.y, kh[2*j], kl[2*j]);
            split2(kv.z, kv.w, kh[2*j+1], kl[2*j+1]);
            float4 vv = *reinterpret_cast<const float4*>(vptr + j * 4);
            split2(vv.x, vv.y, vh[2*j], vl[2*j]);
            split2(vv.z, vv.w, vh[2*j+1], vl[2*j+1]);
        }
        char* sp = (char*)smbuf;
        const int bc = ke0 * 2;
        *reinterpret_cast<uint4*>(sp + swz(SM_KH, kc, bc))    = make_uint4(kh[0],kh[1],kh[2],kh[3]);
        *reinterpret_cast<uint4*>(sp + swz(SM_KH, kc, bc+16)) = make_uint4(kh[4],kh[5],kh[6],kh[7]);
        *reinterpret_cast<uint4*>(sp + swz(SM_KL, kc, bc))    = make_uint4(kl[0],kl[1],kl[2],kl[3]);
        *reinterpret_cast<uint4*>(sp + swz(SM_KL, kc, bc+16)) = make_uint4(kl[4],kl[5],kl[6],kl[7]);
        *reinterpret_cast<uint4*>(sp + swz(SM_VH, kc, bc))    = make_uint4(vh[0],vh[1],vh[2],vh[3]);
        *reinterpret_cast<uint4*>(sp + swz(SM_VH, kc, bc+16)) = make_uint4(vh[4],vh[5],vh[6],vh[7]);
        *reinterpret_cast<uint4*>(sp + swz(SM_VL, kc, bc))    = make_uint4(vl[0],vl[1],vl[2],vl[3]);
        *reinterpret_cast<uint4*>(sp + swz(SM_VL, kc, bc+16)) = make_uint4(vl[4],vl[5],vl[6],vl[7]);
    }
    __syncthreads();

    for (int tile = 0; tile < NTILES; tile++) {
        // ---- prefetch next tile (fp32) into registers ----
        float4 kx[4], vx[4];
        const bool pf = (tile + 1 < NTILES);
        if (pf) {
            const float* kp = kptr + (size_t)(tile + 1) * tstep;
            const float* vp = vptr + (size_t)(tile + 1) * tstep;
            #pragma unroll
            for (int j = 0; j < 4; j++) {
                kx[j] = *reinterpret_cast<const float4*>(kp + j * 4);
                vx[j] = *reinterpret_cast<const float4*>(vp + j * 4);
            }
        }

        // ---- QK^T: sacc[nblock][4] ----
        float sacc[8][4];
        #pragma unroll
        for (int j = 0; j < 8; j++)
            #pragma unroll
            for (int i = 0; i < 4; i++) sacc[j][i] = 0.0f;

        #pragma unroll
        for (int jj = 0; jj < 4; jj++) {        // nblock pairs (n = 16jj..16jj+15)
            #pragma unroll
            for (int kb = 0; kb < 4; kb++) {    // k blocks (e = 16kb..)
                const unsigned la = swz(sb, 16*jj + (lane & 15), kb*32 + (lane >> 4)*16);
                unsigned bh4[4], bl4[4];
                ldsm_x4(bh4, la + SM_KH);
                ldsm_x4(bl4, la + SM_KL);
                // r0/r2 = nblock 2jj (k lo/hi), r1/r3 = nblock 2jj+1
                mma16816(sacc[2*jj],   &qh[kb*4], bh4[0], bh4[2]);
                mma16816(sacc[2*jj],   &qh[kb*4], bl4[0], bl4[2]);
                mma16816(sacc[2*jj],   &ql[kb*4], bh4[0], bh4[2]);
                mma16816(sacc[2*jj+1], &qh[kb*4], bh4[1], bh4[3]);
                mma16816(sacc[2*jj+1], &qh[kb*4], bl4[1], bl4[3]);
                mma16816(sacc[2*jj+1], &ql[kb*4], bh4[1], bh4[3]);
            }
        }

        // ---- online softmax (rows g and g+8, quad reduction) ----
        float mx0 = -1e30f, mx1 = -1e30f;
        #pragma unroll
        for (int j = 0; j < 8; j++) {
            mx0 = fmaxf(mx0, fmaxf(sacc[j][0], sacc[j][1]));
            mx1 = fmaxf(mx1, fmaxf(sacc[j][2], sacc[j][3]));
        }
        #pragma unroll
        for (int off = 1; off < 4; off <<= 1) {
            mx0 = fmaxf(mx0, __shfl_xor_sync(0xffffffffu, mx0, off));
            mx1 = fmaxf(mx1, __shfl_xor_sync(0xffffffffu, mx1, off));
        }
        const float nm0 = fmaxf(m0, mx0), nm1 = fmaxf(m1, mx1);
        const float a0 = __expf(m0 - nm0), a1 = __expf(m1 - nm1);
        m0 = nm0; m1 = nm1;

        float rs0 = 0.0f, rs1 = 0.0f;
        #pragma unroll
        for (int j = 0; j < 8; j++) {
            sacc[j][0] = __expf(sacc[j][0] - nm0);
            sacc[j][1] = __expf(sacc[j][1] - nm0);
            sacc[j][2] = __expf(sacc[j][2] - nm1);
            sacc[j][3] = __expf(sacc[j][3] - nm1);
            rs0 += sacc[j][0] + sacc[j][1];
            rs1 += sacc[j][2] + sacc[j][3];
        }
        #pragma unroll
        for (int off = 1; off < 4; off <<= 1) {
            rs0 += __shfl_xor_sync(0xffffffffu, rs0, off);
            rs1 += __shfl_xor_sync(0xffffffffu, rs1, off);
        }
        l0s = l0s * a0 + rs0;
        l1s = l1s * a1 + rs1;

        // rescale O
        #pragma unroll
        for (int j = 0; j < 8; j++) {
            o[j][0] *= a0; o[j][1] *= a0;
            o[j][2] *= a1; o[j][3] *= a1;
        }

        // ---- pack P into A-fragments (C-frag -> A-frag identity) ----
        unsigned ph[16], pl[16];   // [kb][4]
        #pragma unroll
        for (int kb = 0; kb < 4; kb++) {
            split2(sacc[2*kb][0],   sacc[2*kb][1],   ph[kb*4+0], pl[kb*4+0]);
            split2(sacc[2*kb][2],   sacc[2*kb][3],   ph[kb*4+1], pl[kb*4+1]);
            split2(sacc[2*kb+1][0], sacc[2*kb+1][1], ph[kb*4+2], pl[kb*4+2]);
            split2(sacc[2*kb+1][2], sacc[2*kb+1][3], ph[kb*4+3], pl[kb*4+3]);
        }

        // ---- PV: O += P * V (V via ldmatrix.trans) ----
        #pragma unroll
        for (int jj = 0; jj < 4; jj++) {        // dblock pairs (d = 16jj..16jj+15)
            #pragma unroll
            for (int kb = 0; kb < 4; kb++) {    // s blocks (s = 16kb..)
                const unsigned la = swz(sb, 16*kb + (lane & 15), jj*32 + (lane >> 4)*16);
                unsigned vh4[4], vl4[4];
                ldsm_x4_t(vh4, la + SM_VH);
                ldsm_x4_t(vl4, la + SM_VL);
                // r0/r1 = dblock 2jj (s lo/hi), r2/r3 = dblock 2jj+1
                mma16816(o[2*jj],   &ph[kb*4], vh4[0], vh4[1]);
                mma16816(o[2*jj],   &ph[kb*4], vl4[0], vl4[1]);
                mma16816(o[2*jj],   &pl[kb*4], vh4[0], vh4[1]);
                mma16816(o[2*jj+1], &ph[kb*4], vh4[2], vh4[3]);
                mma16816(o[2*jj+1], &ph[kb*4], vl4[2], vl4[3]);
                mma16816(o[2*jj+1], &pl[kb*4], vh4[2], vh4[3]);
            }
        }

        // ---- store prefetched tile ----
        if (pf) {
            __syncthreads();   // all warps done reading K/V smem
            unsigned kh[8], kl[8], vh[8], vl[8];
            #pragma unroll
            for (int j = 0; j < 4; j++) {
                split2(kx[j].x, kx[j].y, kh[2*j], kl[2*j]);
                split2(kx[j].z, kx[j].w, kh[2*j+1], kl[2*j+1]);
                split2(vx[j].x, vx[j].y, vh[2*j], vl[2*j]);
                split2(vx[j].z, vx[j].w, vh[2*j+1], vl[2*j+1]);
            }
            char* sp = (char*)smbuf;
            const int bc = ke0 * 2;
            *reinterpret_cast<uint4*>(sp + swz(SM_KH, kc, bc))    = make_uint4(kh[0],kh[1],kh[2],kh[3]);
            *reinterpret_cast<uint4*>(sp + swz(SM_KH, kc, bc+16)) = make_uint4(kh[4],kh[5],kh[6],kh[7]);
            *reinterpret_cast<uint4*>(sp + swz(SM_KL, kc, bc))    = make_uint4(kl[0],kl[1],kl[2],kl[3]);
            *reinterpret_cast<uint4*>(sp + swz(SM_KL, kc, bc+16)) = make_uint4(kl[4],kl[5],kl[6],kl[7]);
            *reinterpret_cast<uint4*>(sp + swz(SM_VH, kc, bc))    = make_uint4(vh[0],vh[1],vh[2],vh[3]);
            *reinterpret_cast<uint4*>(sp + swz(SM_VH, kc, bc+16)) = make_uint4(vh[4],vh[5],vh[6],vh[7]);
            *reinterpret_cast<uint4*>(sp + swz(SM_VL, kc, bc))    = make_uint4(vl[0],vl[1],vl[2],vl[3]);
            *reinterpret_cast<uint4*>(sp + swz(SM_VL, kc, bc+16)) = make_uint4(vl[4],vl[5],vl[6],vl[7]);
            __syncthreads();
        }
    }

    // ============ epilogue: normalize + store ============
    const float inv0 = 1.0f / l0s;
    const float inv1 = 1.0f / l1s;
    const int r0 = l0 + wid * 16 + g;
    float* ob0 = O + ((size_t)(b * L_Q + r0)     * H_N + h) * D_N;
    float* ob1 = O + ((size_t)(b * L_Q + r0 + 8) * H_N + h) * D_N;
    #pragma unroll
    for (int j = 0; j < 8; j++) {
        const int d = j * 8 + tg * 2;
        *reinterpret_cast<float2*>(ob0 + d) = make_float2(o[j][0] * inv0, o[j][1] * inv0);
        *reinterpret_cast<float2*>(ob1 + d) = make_float2(o[j][2] * inv1, o[j][3] * inv1);
    }
}

extern "C" void kernel_launch(void* const* d_in, const int* in_sizes, int n_in,
                              void* d_out, int out_size)
{
    const float* Q = (const float*)d_in[0];
    const float* K = (const float*)d_in[1];
    const float* V = (const float*)d_in[2];
    float* O = (float*)d_out;
    (void)in_sizes; (void)n_in; (void)out_size;

    dim3 grid(L_Q / BM, B_SZ * H_N);   // 16 x 32 = 512 CTAs
    fullattn_hmma_kernel<<<grid, NT>>>(Q, K, V, O);
}